// round 7
// baseline (speedup 1.0000x reference)
#include <cuda_runtime.h>
#include <stdint.h>

// ---------------------------------------------------------------------------
// Sparse average pooling, single fused persistent kernel.
//
// Effective reference key (JAX x64 disabled -> int32 wrap drops the batch
// term): q0*2^22 + q1*2^11 + q2, q_i = coord_i>>1 < 512. Order-isomorphic
// 27-bit key (q0<<18)|(q1<<9)|q2. Presence bitmap = 16MB (L2-resident).
// rank = # distinct smaller keys present = jnp.unique inverse (proven
// equivalent to the CUB sort pipeline in earlier rounds).
//
// All 9 former kernels fused into one launch with software grid barriers
// (generation counter; replay-safe: count self-resets, gen is monotonic).
// ---------------------------------------------------------------------------

#define NBM_WORDS (1u << 22)   // 2^27 bits / 32 = 16 MB
#define NSEG      (1u << 17)   // 1024-bit segments
#define NCHUNK    128          // NSEG / 1024
#define MAXN      (1  << 21)
#define NBLOCKS   592          // 148 SMs x 4 blocks (GB300 has 152 SMs)
#define NTHREADS  256

__device__ uint32_t g_bitmap[NBM_WORDS];
__device__ uint32_t g_segpref[NSEG];
__device__ uint32_t g_part[NCHUNK];
__device__ uint32_t g_counts[MAXN];
__device__ uint32_t g_ranks[MAXN];

__device__ unsigned g_bar_count = 0;
__device__ volatile unsigned g_bar_gen = 0;

__device__ __forceinline__ void grid_bar() {
    __syncthreads();
    if (threadIdx.x == 0) {
        __threadfence();
        unsigned gen = g_bar_gen;
        if (atomicAdd(&g_bar_count, 1u) == gridDim.x - 1u) {
            g_bar_count = 0u;
            __threadfence();
            g_bar_gen = gen + 1u;
        } else {
            while (g_bar_gen == gen) { __nanosleep(64); }
        }
        __threadfence();
    }
    __syncthreads();
}

__device__ __forceinline__ uint32_t make_key(int4 c) {
    uint32_t q0 = ((uint32_t)c.x) >> 1;
    uint32_t q1 = ((uint32_t)c.y) >> 1;
    uint32_t q2 = ((uint32_t)c.z) >> 1;
    return (q0 << 18) | (q1 << 9) | q2;   // batch excluded (int32 wrap in ref)
}

__global__ void __launch_bounds__(NTHREADS, 4)
fused_pool(const int* __restrict__ coords, const float* __restrict__ feats,
           float* __restrict__ outc, float* __restrict__ outf, int n) {
    const uint32_t tid = blockIdx.x * NTHREADS + threadIdx.x;
    const uint32_t NT  = gridDim.x * NTHREADS;
    const uint32_t un  = (uint32_t)n;
    const int4* c4 = reinterpret_cast<const int4*>(coords);
    __shared__ uint32_t sh[NTHREADS];

    // ---- A: zero bitmap + counts ----
    {
        uint4 z = make_uint4(0u, 0u, 0u, 0u);
        uint4* bm = reinterpret_cast<uint4*>(g_bitmap);
        for (uint32_t i = tid; i < NBM_WORDS / 4; i += NT) bm[i] = z;
        for (uint32_t i = tid; i < un; i += NT) g_counts[i] = 0u;
    }
    grid_bar();

    // ---- B: set presence bits ----
    for (uint32_t i = tid; i < un; i += NT) {
        uint32_t key = make_key(c4[i]);
        atomicOr(&g_bitmap[key >> 5], 1u << (key & 31u));
    }
    grid_bar();

    // ---- C1: per-segment popcount (warp per 1024-bit segment) ----
    {
        uint32_t gw = tid >> 5, lane = tid & 31u, nw = NT >> 5;
        for (uint32_t s = gw; s < NSEG; s += nw) {
            uint32_t v = g_bitmap[(s << 5) + lane];
            uint32_t c = __reduce_add_sync(0xffffffffu, __popc(v));
            if (lane == 0) g_segpref[s] = c;
        }
    }
    grid_bar();

    // ---- C2: exclusive scan within 1024-segment chunks (first 128 blocks) ----
    if (blockIdx.x < NCHUNK) {
        uint32_t base = blockIdx.x * 1024u + threadIdx.x * 4u;
        uint32_t v0 = g_segpref[base], v1 = g_segpref[base + 1];
        uint32_t v2 = g_segpref[base + 2], v3 = g_segpref[base + 3];
        uint32_t s01 = v0 + v1;
        uint32_t tsum = s01 + v2 + v3;
        sh[threadIdx.x] = tsum;
        __syncthreads();
        for (int off = 1; off < NTHREADS; off <<= 1) {
            uint32_t t = 0;
            if ((int)threadIdx.x >= off) t = sh[threadIdx.x - off];
            __syncthreads();
            if ((int)threadIdx.x >= off) sh[threadIdx.x] += t;
            __syncthreads();
        }
        uint32_t excl = sh[threadIdx.x] - tsum;
        g_segpref[base]     = excl;
        g_segpref[base + 1] = excl + v0;
        g_segpref[base + 2] = excl + s01;
        g_segpref[base + 3] = excl + s01 + v2;
        if (threadIdx.x == NTHREADS - 1) g_part[blockIdx.x] = sh[threadIdx.x];
    }
    grid_bar();

    // ---- C3: exclusive scan of the 128 chunk sums (block 0, all threads) ----
    if (blockIdx.x == 0) {
        uint32_t v = (threadIdx.x < NCHUNK) ? g_part[threadIdx.x] : 0u;
        sh[threadIdx.x] = v;
        __syncthreads();
        for (int off = 1; off < NTHREADS; off <<= 1) {
            uint32_t t = 0;
            if ((int)threadIdx.x >= off) t = sh[threadIdx.x - off];
            __syncthreads();
            if ((int)threadIdx.x >= off) sh[threadIdx.x] += t;
            __syncthreads();
        }
        if (threadIdx.x < NCHUNK) g_part[threadIdx.x] = sh[threadIdx.x] - v;
    }
    grid_bar();

    // ---- D: per-point rank + voxel counts ----
    for (uint32_t i = tid; i < un; i += NT) {
        uint32_t key  = make_key(c4[i]);
        uint32_t bit  = key & 31u;
        uint32_t w    = key >> 5;
        uint32_t seg  = w >> 5;
        uint32_t widx = w & 31u;
        uint32_t r = g_part[seg >> 10] + g_segpref[seg];
        uint32_t mask = (1u << bit) - 1u;
        const uint4* p = reinterpret_cast<const uint4*>(&g_bitmap[seg << 5]);
#pragma unroll
        for (int j = 0; j < 8; j++) {
            uint4 v = p[j];
            uint32_t base = (uint32_t)(j * 4);
#pragma unroll
            for (int k = 0; k < 4; k++) {
                uint32_t word = (k == 0) ? v.x : (k == 1) ? v.y : (k == 2) ? v.z : v.w;
                uint32_t idx = base + (uint32_t)k;
                if (idx < widx)       r += __popc(word);
                else if (idx == widx) r += __popc(word & mask);
            }
        }
        g_ranks[i] = r;
        atomicAdd(&g_counts[r], 1u);
    }
    grid_bar();

    // ---- E: zero empty/multi output slots (count==1 slots need no init) ----
    for (uint32_t s = tid; s < un; s += NT) {
        if (g_counts[s] != 1u) {
            float4 z = make_float4(0.f, 0.f, 0.f, 0.f);
            reinterpret_cast<float4*>(outc + 4ull * s)[0] = z;
            float4* f = reinterpret_cast<float4*>(outf + 64ull * s);
#pragma unroll
            for (int j = 0; j < 16; j++) f[j] = z;
        }
    }
    grid_bar();

    // ---- F: scatter (warp per point) ----
    {
        uint32_t gw = tid >> 5, lane = tid & 31u, nw = NT >> 5;
        for (uint32_t p = gw; p < un; p += nw) {
            uint32_t r = g_ranks[p];
            uint32_t c = g_counts[r];
            float2 v = reinterpret_cast<const float2*>(feats + 64ull * p)[lane];
            float2* fo = reinterpret_cast<float2*>(outf + 64ull * r);
            if (c == 1u) {
                fo[lane] = v;
                if (lane < 4u) outc[4ull * r + lane] = (float)coords[4ull * p + lane];
            } else {
                float* fs = outf + 64ull * r + 2ull * lane;
                atomicAdd(fs, v.x);
                atomicAdd(fs + 1, v.y);
                if (lane < 4u) atomicAdd(&outc[4ull * r + lane], (float)coords[4ull * p + lane]);
            }
        }
    }
    grid_bar();

    // ---- G: finalize multi-point voxels ----
    for (uint32_t s = tid; s < un; s += NT) {
        uint32_t c = g_counts[s];
        if (c > 1u) {
            float fc = (float)c;
#pragma unroll
            for (int j = 0; j < 4; j++)
                outc[4ull * s + j] = rintf(outc[4ull * s + j] / fc);
#pragma unroll
            for (int j = 0; j < 64; j++)
                outf[64ull * s + j] = outf[64ull * s + j] / fc;
        }
    }
}

extern "C" void kernel_launch(void* const* d_in, const int* in_sizes, int n_in,
                              void* d_out, int out_size) {
    // coords is the smaller input (4 ints/point) vs feats (64 floats/point)
    const int*   coords;
    const float* feats;
    int n;
    if (in_sizes[0] <= in_sizes[1]) {
        coords = (const int*)d_in[0];
        feats  = (const float*)d_in[1];
        n = in_sizes[0] / 4;
    } else {
        coords = (const int*)d_in[1];
        feats  = (const float*)d_in[0];
        n = in_sizes[1] / 4;
    }
    if (n <= 0 || n > MAXN) return;

    float* outc = (float*)d_out;             // [n,4]  pooled coords (as f32)
    float* outf = outc + 4ull * (size_t)n;   // [n,64] pooled feats

    fused_pool<<<NBLOCKS, NTHREADS>>>(coords, feats, outc, outf, n);
}

// round 8
// speedup vs baseline: 3.1396x; 3.1396x over previous
#include <cuda_runtime.h>
#include <stdint.h>

// ---------------------------------------------------------------------------
// Sparse average pooling via L2-resident presence-bitmap ranks (discrete
// kernels — proven fastest structure; fused persistent version regressed).
//
// Effective reference key (JAX x64 disabled -> int32 wrap drops batch term):
//   q0*2^22 + q1*2^11 + q2, q_i = coord_i>>1 < 512.
// Order-isomorphic 27-bit key (q0<<18)|(q1<<9)|q2. Bitmap 16MB, L2-resident.
// rank = # distinct smaller keys = jnp.unique inverse (sort-equivalent,
// verified). ~99.2% of points are singleton voxels -> direct-store fast path.
// ---------------------------------------------------------------------------

#define NBM_WORDS (1u << 22)   // 2^27 bits / 32 words = 16 MB
#define NSEG      (1u << 18)   // 512-bit (16-word, 64B) segments
#define NCHUNK    256          // NSEG / 1024
#define MAXN      (1  << 21)

__device__ uint32_t g_bitmap[NBM_WORDS];
__device__ uint32_t g_segpref[NSEG];   // per-segment popcount -> chunk-local excl prefix
__device__ uint32_t g_part[NCHUNK];    // chunk sums -> exclusive prefix
__device__ uint32_t g_counts[MAXN];
__device__ uint32_t g_ranks[MAXN];
__device__ uint32_t g_multi[MAXN];     // worklist of multi-point voxel slots
__device__ uint32_t g_nmulti;

__device__ __forceinline__ uint32_t make_key(int4 c) {
    uint32_t q0 = ((uint32_t)c.x) >> 1;
    uint32_t q1 = ((uint32_t)c.y) >> 1;
    uint32_t q2 = ((uint32_t)c.z) >> 1;
    return (q0 << 18) | (q1 << 9) | q2;   // batch excluded (int32 wrap in ref)
}

// A: zero bitmap + counts + worklist counter
__global__ void k_zero(int n) {
    uint32_t tid = blockIdx.x * blockDim.x + threadIdx.x;
    uint32_t stride = gridDim.x * blockDim.x;
    uint4 z = make_uint4(0u, 0u, 0u, 0u);
    uint4* bm = reinterpret_cast<uint4*>(g_bitmap);
    for (uint32_t i = tid; i < NBM_WORDS / 4; i += stride) bm[i] = z;
    for (uint32_t i = tid; i < (uint32_t)n; i += stride) g_counts[i] = 0u;
    if (tid == 0) g_nmulti = 0u;
}

// B: set presence bits
__global__ void k_setbits(const int4* __restrict__ coords, int n) {
    int i = blockIdx.x * blockDim.x + threadIdx.x;
    if (i >= n) return;
    uint32_t key = make_key(coords[i]);
    atomicOr(&g_bitmap[key >> 5], 1u << (key & 31u));
}

// C: per-segment popcount. Warp covers 2 segments (32 words, coalesced);
//    16-lane halves reduce independently.
__global__ void k_segcnt() {
    uint32_t gw   = (blockIdx.x * blockDim.x + threadIdx.x) >> 5;
    uint32_t lane = threadIdx.x & 31u;
    if (gw >= NSEG / 2) return;
    uint32_t v = __popc(g_bitmap[(gw << 5) + lane]);
#pragma unroll
    for (int off = 8; off >= 1; off >>= 1)
        v += __shfl_xor_sync(0xffffffffu, v, off, 16);
    if ((lane & 15u) == 0) g_segpref[(gw << 1) + (lane >> 4)] = v;
}

// D: exclusive scan of segment counts within 1024-segment chunks
__global__ void k_scan1() {
    __shared__ uint32_t sh[256];
    uint32_t base = blockIdx.x * 1024u + threadIdx.x * 4u;
    uint4 v = reinterpret_cast<const uint4*>(g_segpref)[base >> 2];
    uint32_t s01 = v.x + v.y;
    uint32_t tsum = s01 + v.z + v.w;
    sh[threadIdx.x] = tsum;
    __syncthreads();
    for (int off = 1; off < 256; off <<= 1) {
        uint32_t t = 0;
        if ((int)threadIdx.x >= off) t = sh[threadIdx.x - off];
        __syncthreads();
        if ((int)threadIdx.x >= off) sh[threadIdx.x] += t;
        __syncthreads();
    }
    uint32_t excl = sh[threadIdx.x] - tsum;
    uint4 o;
    o.x = excl; o.y = excl + v.x; o.z = excl + s01; o.w = excl + s01 + v.z;
    reinterpret_cast<uint4*>(g_segpref)[base >> 2] = o;
    if (threadIdx.x == 255) g_part[blockIdx.x] = sh[threadIdx.x];
}

// E: exclusive scan of the 256 chunk sums
__global__ void k_scan2() {
    __shared__ uint32_t sh[NCHUNK];
    uint32_t v = g_part[threadIdx.x];
    sh[threadIdx.x] = v;
    __syncthreads();
    for (int off = 1; off < NCHUNK; off <<= 1) {
        uint32_t t = 0;
        if ((int)threadIdx.x >= off) t = sh[threadIdx.x - off];
        __syncthreads();
        if ((int)threadIdx.x >= off) sh[threadIdx.x] += t;
        __syncthreads();
    }
    g_part[threadIdx.x] = sh[threadIdx.x] - v;
}

// F: per-point rank + counts + multi-voxel worklist (old==1 -> 2nd arrival)
__global__ void k_rank(const int4* __restrict__ coords, int n) {
    int i = blockIdx.x * blockDim.x + threadIdx.x;
    if (i >= n) return;
    uint32_t key  = make_key(coords[i]);
    uint32_t bit  = key & 31u;
    uint32_t w    = key >> 5;
    uint32_t seg  = w >> 4;          // 16 words per segment
    uint32_t widx = w & 15u;
    uint32_t r = g_part[seg >> 10] + g_segpref[seg];
    uint32_t mask = (1u << bit) - 1u;
    const uint4* p = reinterpret_cast<const uint4*>(&g_bitmap[seg << 4]);
#pragma unroll
    for (int j = 0; j < 4; j++) {
        uint4 v = p[j];
        uint32_t base = (uint32_t)(j * 4);
#pragma unroll
        for (int k = 0; k < 4; k++) {
            uint32_t word = (k == 0) ? v.x : (k == 1) ? v.y : (k == 2) ? v.z : v.w;
            uint32_t idx = base + (uint32_t)k;
            if (idx < widx)       r += __popc(word);
            else if (idx == widx) r += __popc(word & mask);
        }
    }
    g_ranks[i] = r;
    uint32_t old = atomicAdd(&g_counts[r], 1u);
    if (old == 1u) {                     // exactly one point per multi voxel
        uint32_t s = atomicAdd(&g_nmulti, 1u);
        g_multi[s] = r;
    }
}

// H: unconditional direct store, half-warp (16 lanes, float4) per point.
//    Races on multi slots are benign: k_prep re-zeros them afterwards.
__global__ void k_direct(const int* __restrict__ coords, const float* __restrict__ feats,
                         float* __restrict__ outc, float* __restrict__ outf, int n) {
    uint32_t gw   = (blockIdx.x * blockDim.x + threadIdx.x) >> 5;
    uint32_t lane = threadIdx.x & 31u;
    uint32_t half = lane >> 4;            // 0 or 1
    uint32_t hl   = lane & 15u;
    uint32_t pt   = gw * 2u + half;
    if (pt >= (uint32_t)n) return;
    uint32_t r = g_ranks[pt];
    float4 v = reinterpret_cast<const float4*>(feats + 64ull * pt)[hl];
    reinterpret_cast<float4*>(outf + 64ull * r)[hl] = v;
    if (hl == 0) {
        int4 c = reinterpret_cast<const int4*>(coords)[pt];
        float4 cf = make_float4((float)c.x, (float)c.y, (float)c.z, (float)c.w);
        reinterpret_cast<float4*>(outc + 4ull * r)[0] = cf;
    }
}

// G: zero all non-singleton slots (empty ~0.4% + multi ~0.4%)
__global__ void k_prep(float* __restrict__ outc, float* __restrict__ outf, int n) {
    int s = blockIdx.x * blockDim.x + threadIdx.x;
    if (s >= n) return;
    if (g_counts[s] != 1u) {
        float4 z = make_float4(0.f, 0.f, 0.f, 0.f);
        reinterpret_cast<float4*>(outc + 4ull * s)[0] = z;
        float4* f = reinterpret_cast<float4*>(outf + 64ull * s);
#pragma unroll
        for (int j = 0; j < 16; j++) f[j] = z;
    }
}

// I: atomic accumulate for multi-voxel points only (warp ballot + cooperative)
__global__ void k_multi(const int* __restrict__ coords, const float* __restrict__ feats,
                        float* __restrict__ outc, float* __restrict__ outf, int n) {
    uint32_t gw   = (blockIdx.x * blockDim.x + threadIdx.x) >> 5;
    uint32_t lane = threadIdx.x & 31u;
    uint32_t pt   = gw * 32u + lane;
    bool valid = pt < (uint32_t)n;
    uint32_t r = valid ? g_ranks[pt] : 0u;
    uint32_t c = valid ? g_counts[r] : 0u;
    uint32_t m = __ballot_sync(0xffffffffu, valid && c > 1u);
    while (m) {
        uint32_t j = __ffs(m) - 1u;
        m &= m - 1u;
        uint32_t rj  = __shfl_sync(0xffffffffu, r, j);
        uint32_t ptj = gw * 32u + j;
        float2 v = reinterpret_cast<const float2*>(feats + 64ull * ptj)[lane];
        float* fs = outf + 64ull * rj + 2ull * lane;
        atomicAdd(fs, v.x);
        atomicAdd(fs + 1, v.y);
        if (lane < 4u)
            atomicAdd(&outc[4ull * rj + lane], (float)coords[4ull * ptj + lane]);
    }
}

// J: finalize multi voxels from worklist (warp per voxel; grid-stride)
__global__ void k_final(float* __restrict__ outc, float* __restrict__ outf) {
    uint32_t gw   = (blockIdx.x * blockDim.x + threadIdx.x) >> 5;
    uint32_t lane = threadIdx.x & 31u;
    uint32_t nw   = (gridDim.x * blockDim.x) >> 5;
    uint32_t nm   = g_nmulti;
    for (uint32_t v = gw; v < nm; v += nw) {
        uint32_t r = g_multi[v];
        float fc = (float)g_counts[r];
        float* f = outf + 64ull * r + 2ull * lane;
        f[0] = f[0] / fc;
        f[1] = f[1] / fc;
        if (lane < 4u) {
            float* cc = outc + 4ull * r + lane;
            cc[0] = rintf(cc[0] / fc);
        }
    }
}

extern "C" void kernel_launch(void* const* d_in, const int* in_sizes, int n_in,
                              void* d_out, int out_size) {
    // coords is the smaller input (4 ints/point) vs feats (64 floats/point)
    const int*   coords;
    const float* feats;
    int n;
    if (in_sizes[0] <= in_sizes[1]) {
        coords = (const int*)d_in[0];
        feats  = (const float*)d_in[1];
        n = in_sizes[0] / 4;
    } else {
        coords = (const int*)d_in[1];
        feats  = (const float*)d_in[0];
        n = in_sizes[1] / 4;
    }
    if (n <= 0 || n > MAXN) return;

    float* outc = (float*)d_out;             // [n,4]  pooled coords (as f32)
    float* outf = outc + 4ull * (size_t)n;   // [n,64] pooled feats

    const int4* c4 = reinterpret_cast<const int4*>(coords);
    int nb = (n + 255) / 256;

    k_zero<<<2048, 256>>>(n);
    k_setbits<<<nb, 256>>>(c4, n);
    k_segcnt<<<(int)((NSEG / 2 * 32 + 255) / 256), 256>>>();
    k_scan1<<<NCHUNK, 256>>>();
    k_scan2<<<1, NCHUNK>>>();
    k_rank<<<nb, 256>>>(c4, n);
    {
        long long threads = 32ll * ((n + 1) / 2);
        k_direct<<<(int)((threads + 255) / 256), 256>>>(coords, feats, outc, outf, n);
    }
    k_prep<<<nb, 256>>>(outc, outf, n);
    k_multi<<<nb, 256>>>(coords, feats, outc, outf, n);
    k_final<<<512, 256>>>(outc, outf);
}

// round 9
// speedup vs baseline: 3.3288x; 1.0603x over previous
#include <cuda_runtime.h>
#include <stdint.h>

// ---------------------------------------------------------------------------
// Sparse average pooling via L2-resident presence-bitmap ranks.
//
// Effective reference key (JAX x64 disabled -> int32 wrap drops batch term):
//   q0*2^22 + q1*2^11 + q2, q_i = coord_i>>1 < 512.
// Order-isomorphic 27-bit key (q0<<18)|(q1<<9)|q2. Bitmap 16MB, L2-resident.
// rank = # distinct smaller keys = jnp.unique inverse (sort-equivalent,
// verified). Ranks are DENSE in [0,nvox): empty slots = contiguous tail.
// ---------------------------------------------------------------------------

#define NBM_WORDS (1u << 22)    // 2^27 bits / 32 = 16 MB
#define SEGW      8u            // 8 words = 256 bits = 32B per segment
#define NSEG      (NBM_WORDS / SEGW)        // 524288 segments
#define CHUNK_SEGS 1024u
#define NCHUNKB   (NSEG / CHUNK_SEGS)       // 512 scan chunks
#define MAXN      (1 << 21)

__device__ uint32_t g_bitmap[NBM_WORDS];
__device__ uint32_t g_segpref[NSEG];   // ABSOLUTE exclusive prefix per segment
__device__ uint32_t g_state[NCHUNKB];  // decoupled-lookback state (val<<2 | flag)
__device__ uint32_t g_counts[MAXN];
__device__ uint32_t g_ranks[MAXN];
__device__ uint32_t g_multi[MAXN];     // worklist of multi-point voxel slots
__device__ uint32_t g_nmulti;
__device__ uint32_t g_nvox;            // number of unique voxels

__device__ __forceinline__ uint32_t make_key(int4 c) {
    uint32_t q0 = ((uint32_t)c.x) >> 1;
    uint32_t q1 = ((uint32_t)c.y) >> 1;
    uint32_t q2 = ((uint32_t)c.z) >> 1;
    return (q0 << 18) | (q1 << 9) | q2;   // batch excluded (int32 wrap in ref)
}

__device__ __forceinline__ uint32_t popc4(uint4 v) {
    return __popc(v.x) + __popc(v.y) + __popc(v.z) + __popc(v.w);
}

// A: zero bitmap + counts + scan state + worklist counter
__global__ void k_zero(int n) {
    uint32_t tid = blockIdx.x * blockDim.x + threadIdx.x;
    uint32_t stride = gridDim.x * blockDim.x;
    uint4 z = make_uint4(0u, 0u, 0u, 0u);
    uint4* bm = reinterpret_cast<uint4*>(g_bitmap);
    for (uint32_t i = tid; i < NBM_WORDS / 4; i += stride) bm[i] = z;
    for (uint32_t i = tid; i < (uint32_t)n; i += stride) g_counts[i] = 0u;
    for (uint32_t i = tid; i < NCHUNKB; i += stride) g_state[i] = 0u;
    if (tid == 0) g_nmulti = 0u;
}

// B: set presence bits
__global__ void k_setbits(const int4* __restrict__ coords, int n) {
    int i = blockIdx.x * blockDim.x + threadIdx.x;
    if (i >= n) return;
    uint32_t key = make_key(coords[i]);
    atomicOr(&g_bitmap[key >> 5], 1u << (key & 31u));
}

// C: fused popcount + scan, decoupled lookback. Block b handles 1024 segments
//    (32KB of bitmap); writes ABSOLUTE exclusive prefix per segment.
__global__ void __launch_bounds__(256) k_scan() {
    __shared__ uint32_t sh[256];
    __shared__ uint32_t sh_excl;
    uint32_t b = blockIdx.x, t = threadIdx.x;
    uint32_t segBase = b * CHUNK_SEGS + t * 4u;   // 4 segments per thread
    const uint4* p = reinterpret_cast<const uint4*>(&g_bitmap[segBase * SEGW]);
    uint4 w0 = p[0], w1 = p[1], w2 = p[2], w3 = p[3];
    uint4 w4 = p[4], w5 = p[5], w6 = p[6], w7 = p[7];
    uint32_t s0 = popc4(w0) + popc4(w1);
    uint32_t s1 = popc4(w2) + popc4(w3);
    uint32_t s2 = popc4(w4) + popc4(w5);
    uint32_t s3 = popc4(w6) + popc4(w7);
    uint32_t tsum = s0 + s1 + s2 + s3;
    sh[t] = tsum;
    __syncthreads();
    for (int off = 1; off < 256; off <<= 1) {
        uint32_t v = 0;
        if ((int)t >= off) v = sh[t - off];
        __syncthreads();
        if ((int)t >= off) sh[t] += v;
        __syncthreads();
    }
    uint32_t texcl = sh[t] - tsum;

    if (t == 0) {
        uint32_t total = sh[255];
        uint32_t excl;
        if (b == 0) {
            atomicExch(&g_state[0], (total << 2) | 2u);
            excl = 0u;
        } else {
            atomicExch(&g_state[b], (total << 2) | 1u);   // aggregate ready
            uint32_t sum = 0; int i = (int)b - 1;
            while (true) {
                uint32_t v = atomicOr(&g_state[i], 0u);
                uint32_t f = v & 3u;
                if (f == 0u) { __nanosleep(20); continue; }
                sum += v >> 2;
                if (f == 2u) break;
                --i;
            }
            atomicExch(&g_state[b], ((sum + total) << 2) | 2u);  // inclusive
            excl = sum;
        }
        sh_excl = excl;
        if (b == NCHUNKB - 1) g_nvox = excl + total;
    }
    __syncthreads();
    uint32_t base = sh_excl + texcl;
    g_segpref[segBase]     = base;
    g_segpref[segBase + 1] = base + s0;
    g_segpref[segBase + 2] = base + s0 + s1;
    g_segpref[segBase + 3] = base + s0 + s1 + s2;
}

// D: per-point rank (32B bitmap read) + counts + multi-voxel worklist
__global__ void k_rank(const int4* __restrict__ coords, int n) {
    int i = blockIdx.x * blockDim.x + threadIdx.x;
    if (i >= n) return;
    uint32_t key  = make_key(coords[i]);
    uint32_t bit  = key & 31u;
    uint32_t w    = key >> 5;
    uint32_t seg  = w >> 3;          // 8 words per segment
    uint32_t widx = w & 7u;
    uint32_t r = g_segpref[seg];
    uint32_t mask = (1u << bit) - 1u;
    const uint4* p = reinterpret_cast<const uint4*>(&g_bitmap[seg << 3]);
    uint4 a = p[0], b4 = p[1];
    uint32_t words[8] = {a.x, a.y, a.z, a.w, b4.x, b4.y, b4.z, b4.w};
#pragma unroll
    for (uint32_t idx = 0; idx < 8; idx++) {
        if (idx < widx)       r += __popc(words[idx]);
        else if (idx == widx) r += __popc(words[idx] & mask);
    }
    g_ranks[i] = r;
    uint32_t old = atomicAdd(&g_counts[r], 1u);
    if (old == 1u) {                     // second arrival -> multi voxel
        uint32_t s = atomicAdd(&g_nmulti, 1u);
        g_multi[s] = r;
    }
}

// E: unconditional direct store; quarter-warp (8 lanes) x 2 float4 per point.
//    Races on multi slots are benign: k_prep re-zeros them afterwards.
__global__ void k_direct(const int* __restrict__ coords, const float* __restrict__ feats,
                         float* __restrict__ outc, float* __restrict__ outf, int n) {
    uint32_t gw   = (blockIdx.x * blockDim.x + threadIdx.x) >> 5;
    uint32_t lane = threadIdx.x & 31u;
    uint32_t q    = lane >> 3;            // 0..3: point within warp
    uint32_t ql   = lane & 7u;
    uint32_t pt   = gw * 4u + q;
    if (pt >= (uint32_t)n) return;
    uint32_t r = g_ranks[pt];
    const float4* fin = reinterpret_cast<const float4*>(feats + 64ull * pt);
    float4 v0 = __ldcs(fin + ql);
    float4 v1 = __ldcs(fin + ql + 8);
    float4* fo = reinterpret_cast<float4*>(outf + 64ull * r);
    __stcs(fo + ql, v0);
    __stcs(fo + ql + 8, v1);
    if (ql == 0) {
        int4 c = reinterpret_cast<const int4*>(coords)[pt];
        float4 cf = make_float4((float)c.x, (float)c.y, (float)c.z, (float)c.w);
        __stcs(reinterpret_cast<float4*>(outc + 4ull * r), cf);
    }
}

// F: zero the contiguous empty tail [nvox, n) + the multi-slot worklist.
//    (ranks are dense, so these are exactly the non-singleton slots.)
__global__ void k_prep(float* __restrict__ outc, float* __restrict__ outf, int n) {
    uint32_t gw   = (blockIdx.x * blockDim.x + threadIdx.x) >> 5;
    uint32_t lane = threadIdx.x & 31u;
    uint32_t nw   = (gridDim.x * blockDim.x) >> 5;
    uint32_t nv   = g_nvox;
    uint32_t nm   = g_nmulti;
    uint32_t tail = (uint32_t)n - nv;
    uint32_t tot  = tail + nm;
    float4 z = make_float4(0.f, 0.f, 0.f, 0.f);
    for (uint32_t i = gw; i < tot; i += nw) {
        uint32_t s = (i < tail) ? (nv + i) : g_multi[i - tail];
        if (lane < 16u)       reinterpret_cast<float4*>(outf + 64ull * s)[lane] = z;
        else if (lane == 16u) reinterpret_cast<float4*>(outc + 4ull * s)[0] = z;
    }
}

// G: atomic accumulate for multi-voxel points only (warp ballot + cooperative)
__global__ void k_multi(const int* __restrict__ coords, const float* __restrict__ feats,
                        float* __restrict__ outc, float* __restrict__ outf, int n) {
    uint32_t gw   = (blockIdx.x * blockDim.x + threadIdx.x) >> 5;
    uint32_t lane = threadIdx.x & 31u;
    uint32_t pt   = gw * 32u + lane;
    bool valid = pt < (uint32_t)n;
    uint32_t r = valid ? g_ranks[pt] : 0u;
    uint32_t c = valid ? g_counts[r] : 0u;
    uint32_t m = __ballot_sync(0xffffffffu, valid && c > 1u);
    while (m) {
        uint32_t j = __ffs(m) - 1u;
        m &= m - 1u;
        uint32_t rj  = __shfl_sync(0xffffffffu, r, j);
        uint32_t ptj = gw * 32u + j;
        float2 v = reinterpret_cast<const float2*>(feats + 64ull * ptj)[lane];
        float* fs = outf + 64ull * rj + 2ull * lane;
        atomicAdd(fs, v.x);
        atomicAdd(fs + 1, v.y);
        if (lane < 4u)
            atomicAdd(&outc[4ull * rj + lane], (float)coords[4ull * ptj + lane]);
    }
}

// H: finalize multi voxels from worklist (warp per voxel)
__global__ void k_final(float* __restrict__ outc, float* __restrict__ outf) {
    uint32_t gw   = (blockIdx.x * blockDim.x + threadIdx.x) >> 5;
    uint32_t lane = threadIdx.x & 31u;
    uint32_t nw   = (gridDim.x * blockDim.x) >> 5;
    uint32_t nm   = g_nmulti;
    for (uint32_t v = gw; v < nm; v += nw) {
        uint32_t r = g_multi[v];
        float fc = (float)g_counts[r];
        float* f = outf + 64ull * r + 2ull * lane;
        f[0] = f[0] / fc;
        f[1] = f[1] / fc;
        if (lane < 4u) {
            float* cc = outc + 4ull * r + lane;
            cc[0] = rintf(cc[0] / fc);   // half-to-even == jnp.round (exact sums)
        }
    }
}

extern "C" void kernel_launch(void* const* d_in, const int* in_sizes, int n_in,
                              void* d_out, int out_size) {
    // coords is the smaller input (4 ints/point) vs feats (64 floats/point)
    const int*   coords;
    const float* feats;
    int n;
    if (in_sizes[0] <= in_sizes[1]) {
        coords = (const int*)d_in[0];
        feats  = (const float*)d_in[1];
        n = in_sizes[0] / 4;
    } else {
        coords = (const int*)d_in[1];
        feats  = (const float*)d_in[0];
        n = in_sizes[1] / 4;
    }
    if (n <= 0 || n > MAXN) return;

    float* outc = (float*)d_out;             // [n,4]  pooled coords (as f32)
    float* outf = outc + 4ull * (size_t)n;   // [n,64] pooled feats

    const int4* c4 = reinterpret_cast<const int4*>(coords);
    int nb = (n + 255) / 256;

    k_zero<<<2048, 256>>>(n);
    k_setbits<<<nb, 256>>>(c4, n);
    k_scan<<<NCHUNKB, 256>>>();
    k_rank<<<nb, 256>>>(c4, n);
    {
        long long warps = (n + 3) / 4;
        int blocks = (int)((warps * 32 + 255) / 256);
        k_direct<<<blocks, 256>>>(coords, feats, outc, outf, n);
    }
    k_prep<<<256, 256>>>(outc, outf, n);
    k_multi<<<nb, 256>>>(coords, feats, outc, outf, n);
    k_final<<<256, 256>>>(outc, outf);
}